// round 7
// baseline (speedup 1.0000x reference)
#include <cuda_runtime.h>
#include <stdint.h>
#include <math.h>

#define B_     32768
#define D_IN_  256
#define D_OUT_ 256
#define E_     8
#define H_     512
#define GH_    128
#define CAP_   32768

// ---------------- scratch (static __device__, no allocation) ----------------
__device__ int   g_counts[E_];
__device__ int   g_list[E_ * B_];
__device__ float g_wlist[E_ * B_];
__device__ float g_xg[(size_t)E_ * CAP_ * D_IN_];   // gathered inputs (tf32-rounded)
__device__ float g_h1[(size_t)E_ * CAP_ * H_];      // layer-1 activations (tf32-rounded)
__device__ float g_h2[(size_t)E_ * CAP_ * H_];      // layer-2 activations (tf32-rounded)
__device__ float g_wT1[(size_t)E_ * H_ * D_IN_];    // We1^T  [E][512][256] tf32-rounded
__device__ float g_wT2[(size_t)E_ * H_ * H_];       // We2^T  [E][512][512]
__device__ float g_wT3[(size_t)E_ * D_OUT_ * H_];   // We3^T  [E][256][512]

// ---------------- helpers ----------------
__device__ __forceinline__ uint32_t smem_u32(const void* p) {
    uint32_t a;
    asm("{ .reg .u64 t; cvta.to.shared.u64 t, %1; cvt.u32.u64 %0, t; }" : "=r"(a) : "l"(p));
    return a;
}
__device__ __forceinline__ uint32_t f2tf(float x) {
    uint32_t u;
    asm("cvt.rna.tf32.f32 %0, %1;" : "=r"(u) : "f"(x));
    return u;
}
__device__ __forceinline__ void cp16(uint32_t dst, const float* src) {
    asm volatile("cp.async.cg.shared.global [%0], [%1], 16;"
                 :: "r"(dst), "l"(__cvta_generic_to_global(src)) : "memory");
}
#define CP_COMMIT() asm volatile("cp.async.commit_group;" ::: "memory")
#define CP_WAIT1()  asm volatile("cp.async.wait_group 1;" ::: "memory")

__device__ __forceinline__ void ldsm4(uint32_t* r, uint32_t a) {
    asm volatile("ldmatrix.sync.aligned.m8n8.x4.shared.b16 {%0,%1,%2,%3}, [%4];"
                 : "=r"(r[0]), "=r"(r[1]), "=r"(r[2]), "=r"(r[3]) : "r"(a));
}
__device__ __forceinline__ void mma8(float* d, const uint32_t* a, const uint32_t* b) {
    asm volatile(
        "mma.sync.aligned.m16n8k8.row.col.f32.tf32.tf32.f32 "
        "{%0,%1,%2,%3},{%4,%5,%6,%7},{%8,%9},{%0,%1,%2,%3};\n"
        : "+f"(d[0]), "+f"(d[1]), "+f"(d[2]), "+f"(d[3])
        : "r"(a[0]), "r"(a[1]), "r"(a[2]), "r"(a[3]), "r"(b[0]), "r"(b[1]));
}

// ---------------- zero output + counters ----------------
__global__ void zero_kernel(float* __restrict__ out) {
    int i = blockIdx.x * blockDim.x + threadIdx.x;
    int stride = gridDim.x * blockDim.x;
    float4* o4 = (float4*)out;
    const int n4 = (B_ * D_OUT_) / 4;
    for (int j = i; j < n4; j += stride) o4[j] = make_float4(0.f, 0.f, 0.f, 0.f);
    if (blockIdx.x == 0 && threadIdx.x < E_) g_counts[threadIdx.x] = 0;
}

// ---------------- gating (unchanged, proven) ----------------
#define GATE_SMEM_FLOATS 35224
__global__ void __launch_bounds__(256) gating_kernel(
    const float* __restrict__ x,  const float* __restrict__ gW1,
    const float* __restrict__ gb1, const float* __restrict__ gW2,
    const float* __restrict__ gb2)
{
    extern __shared__ float sm[];
    float* shw  = sm;
    float* xs   = sm + 33280;
    float* hid  = sm + 33792;
    float* b1s  = sm + 34048;
    float* w2s  = sm + 34176;
    float* b2s  = sm + 35200;
    float* logt = sm + 35208;

    const int tid = threadIdx.x;
    for (int idx = tid; idx < 256 * 128; idx += 256) {
        int i = idx >> 7, j = idx & 127;
        shw[j * 260 + i] = gW1[idx];
    }
    if (tid < 128) b1s[tid] = gb1[tid];
    for (int idx = tid; idx < 128 * 8; idx += 256) w2s[idx] = gW2[idx];
    if (tid < 8) b2s[tid] = gb2[tid];
    __syncthreads();

    const int j    = tid & 127;
    const int half = tid >> 7;
    for (int p = 0; p < 64; ++p) {
        const int tbase = blockIdx.x * 128 + p * 2;
        const float* xr = x + (size_t)tbase * D_IN_;
        xs[tid]       = xr[tid];
        xs[tid + 256] = xr[tid + 256];
        __syncthreads();

        float acc = 0.f;
        const float4* wr4 = (const float4*)(shw + j * 260);
        const float4* xr4 = (const float4*)(xs + half * 256);
        #pragma unroll
        for (int i4 = 0; i4 < 64; ++i4) {
            float4 w = wr4[i4];
            float4 v = xr4[i4];
            acc = fmaf(w.x, v.x, fmaf(w.y, v.y, fmaf(w.z, v.z, fmaf(w.w, v.w, acc))));
        }
        hid[half * 128 + j] = fmaxf(acc + b1s[j], 0.f);
        __syncthreads();

        if (j < 8) {
            float a = b2s[j];
            const float* hrow = hid + half * 128;
            #pragma unroll 8
            for (int h = 0; h < 128; ++h) a = fmaf(hrow[h], w2s[h * 8 + j], a);
            logt[half * 8 + j] = a;
        }
        __syncthreads();

        if (j == 0) {
            float l[8];
            #pragma unroll
            for (int q = 0; q < 8; ++q) l[q] = logt[half * 8 + q];
            int i1 = 0; float m1 = l[0];
            #pragma unroll
            for (int q = 1; q < 8; ++q) if (l[q] > m1) { m1 = l[q]; i1 = q; }
            int i2 = -1; float m2 = -1e30f;
            #pragma unroll
            for (int q = 0; q < 8; ++q) if (q != i1 && l[q] > m2) { m2 = l[q]; i2 = q; }
            const int t = tbase + half;
            const float ex  = expf(m2 - m1);
            const float den = 1.f + ex;
            int p1 = atomicAdd(&g_counts[i1], 1);
            g_list[i1 * B_ + p1] = t;  g_wlist[i1 * B_ + p1] = 1.f / den;
            int p2 = atomicAdd(&g_counts[i2], 1);
            g_list[i2 * B_ + p2] = t;  g_wlist[i2 * B_ + p2] = ex / den;
        }
        __syncthreads();
    }
}

// ---------------- gather x rows (tf32-rounded) ----------------
__global__ void __launch_bounds__(256) gather_kernel(const float* __restrict__ x) {
    const int e = blockIdx.y;
    const int n = g_counts[e];
    const int row0 = blockIdx.x * 64;
    if (row0 >= n) return;
    for (int v = threadIdx.x; v < 64 * 64; v += 256) {
        int r = row0 + (v >> 6);
        if (r < n) {
            int t = g_list[e * B_ + r];
            float4 s = ((const float4*)(x + (size_t)t * D_IN_))[v & 63];
            uint4 u;
            u.x = f2tf(s.x); u.y = f2tf(s.y); u.z = f2tf(s.z); u.w = f2tf(s.w);
            ((uint4*)(g_xg + ((size_t)e * CAP_ + r) * D_IN_))[v & 63] = u;
        }
    }
}

// ---------------- weight transpose + tf32 round:  out[e][n][k] = rna(in[e][k][n]) ----------------
__global__ void __launch_bounds__(256) transpose_kernel(const float* __restrict__ in, int sel,
                                                        int K, int N) {
    __shared__ float t[32][33];
    float* out = (sel == 1) ? g_wT1 : (sel == 2) ? g_wT2 : g_wT3;
    const int e = blockIdx.z;
    const int k0 = blockIdx.x * 32, n0 = blockIdx.y * 32;
    const float* I = in + (size_t)e * K * N;
    float* O = out + (size_t)e * K * N;
    const int tx = threadIdx.x & 31, ty = threadIdx.x >> 5;   // 32 x 8
    #pragma unroll
    for (int p = 0; p < 32; p += 8)
        t[ty + p][tx] = I[(size_t)(k0 + ty + p) * N + n0 + tx];
    __syncthreads();
    #pragma unroll
    for (int p = 0; p < 32; p += 8)
        O[(size_t)(n0 + ty + p) * K + k0 + tx] = __uint_as_float(f2tf(t[tx][ty + p]));
}

// ---------------- tf32 mma.sync GEMM: 128x128 block, 2x2 warps of 64x64 ----------------
// Smem rows: 36 floats (144B): 16B-aligned for cp.async, conflict-free for ldmatrix.
#define AP 36
#define STG_BYTES   18432              // 128*36*4, per operand per stage
#define STAGE_BYTES 36864              // A + B
#define GEMM_DSMEM  110592             // 3 stages

template<int K, int NTOT, int STAGE, bool RELU, bool SCATTER>
__global__ void __launch_bounds__(128, 2) gemm_mma(const float* __restrict__ bias,
                                                   float* __restrict__ Yout)
{
    const int e = blockIdx.z;
    const int cnt = g_counts[e];
    const int row0 = blockIdx.x * 128;
    if (row0 >= cnt) return;
    const int n0 = blockIdx.y * 128;

    extern __shared__ float dsm[];
    const uint32_t smBase = smem_u32(dsm);
    __shared__ int   stok[128];
    __shared__ float swt[128];

    const int tid = threadIdx.x;
    const int lid = tid & 31, wid = tid >> 5;
    const int g = lid >> 2, tg = lid & 3;
    const int wm = wid >> 1, wn = wid & 1;        // 2 x 2 warps, 64x64 tiles
    const int mb = wm * 64,  nb = wn * 64;

    const float* A  = (STAGE == 1) ? g_xg  : (STAGE == 2) ? g_h1 : g_h2;
    const float* Wt = (STAGE == 1) ? g_wT1 : (STAGE == 2) ? g_wT2 : g_wT3;
    float* Y = SCATTER ? Yout : ((STAGE == 1) ? g_h1 : g_h2);
    const float* Ab = A  + ((size_t)e * CAP_ + row0) * K;
    const float* Bb = Wt + ((size_t)e * NTOT + n0) * K;

    if (SCATTER) {
        int r = row0 + tid;
        stok[tid] = (r < cnt) ? g_list[e * B_ + r] : -1;
        swt[tid]  = (r < cnt) ? g_wlist[e * B_ + r] : 0.f;
    }

    // ldmatrix per-lane base addresses (stage-0 byte offsets)
    const int lane_row = (lid & 7) + (((lid >> 3) & 1) << 3);   // 0..15
    const int lane_k   = (lid >> 4) * 4;                        // 0 or 4
    uint32_t aAddr[4], bAddr[4];
    #pragma unroll
    for (int f = 0; f < 4; ++f)
        aAddr[f] = smBase + ((mb + f * 16 + lane_row) * AP + lane_k) * 4;
    // B x4: mats = (j, kLo), (j, kHi), (j+1, kLo), (j+1, kHi), j = 2*p
    {
        const int grp = lid >> 3;               // 0..3
        #pragma unroll
        for (int p = 0; p < 4; ++p) {
            const int n_loc = nb + (2 * p + (grp >> 1)) * 8 + (lid & 7);
            const int kcol  = (grp & 1) * 4;
            bAddr[p] = smBase + STG_BYTES + (n_loc * AP + kcol) * 4;
        }
    }

    float acc[4][8][4];
    #pragma unroll
    for (int f = 0; f < 4; ++f)
        #pragma unroll
        for (int j = 0; j < 8; ++j)
            #pragma unroll
            for (int q = 0; q < 4; ++q) acc[f][j][q] = 0.f;

    // cp.async staging: 1024 16B chunks per operand, 8 per thread each
    auto stage_copy = [&](int buf, int kt) {
        const uint32_t sb = smBase + buf * STAGE_BYTES;
        const int k0 = kt * 32;
        #pragma unroll
        for (int q = 0; q < 8; ++q) {
            const int c = q * 128 + tid;
            const int r = c >> 3, gg = (c & 7) * 4;
            const uint32_t doff = (r * AP + gg) * 4;
            cp16(sb + doff,             Ab + (size_t)r * K + k0 + gg);
            cp16(sb + STG_BYTES + doff, Bb + (size_t)r * K + k0 + gg);
        }
    };

    constexpr int KT = K / 32;
    stage_copy(0, 0); CP_COMMIT();
    stage_copy(1, 1); CP_COMMIT();
    for (int kt = 0; kt < KT; ++kt) {
        CP_WAIT1();                  // newest group (stage kt+1) may pend; stage kt resident
        __syncthreads();

        const uint32_t so = (kt % 3) * STAGE_BYTES;
        #pragma unroll
        for (int kk = 0; kk < 32; kk += 8) {
            uint32_t af[4][4], bf[8][2];
            #pragma unroll
            for (int f = 0; f < 4; ++f) ldsm4(af[f], aAddr[f] + so + kk * 4);
            #pragma unroll
            for (int p = 0; p < 4; ++p) {
                uint32_t bq[4];
                ldsm4(bq, bAddr[p] + so + kk * 4);
                bf[2 * p][0] = bq[0]; bf[2 * p][1] = bq[1];
                bf[2 * p + 1][0] = bq[2]; bf[2 * p + 1][1] = bq[3];
            }
            #pragma unroll
            for (int f = 0; f < 4; ++f)
                #pragma unroll
                for (int j = 0; j < 8; ++j)
                    mma8(acc[f][j], af[f], bf[j]);
        }
        __syncthreads();             // stage (kt-1)%3 free for reuse
        if (kt + 2 < KT) stage_copy((kt + 2) % 3, kt + 2);
        CP_COMMIT();                 // unconditional: keeps group arithmetic exact
    }

    // ---------------- epilogue ----------------
    const float* Bbias = bias + e * NTOT + n0;
    #pragma unroll
    for (int f = 0; f < 4; ++f) {
        const int rl = mb + f * 16 + g;           // local rows rl, rl+8
        #pragma unroll
        for (int j = 0; j < 8; ++j) {
            const int c = nb + j * 8 + 2 * tg;
            const float b0 = Bbias[c], b1 = Bbias[c + 1];
            float v00 = acc[f][j][0] + b0, v01 = acc[f][j][1] + b1;
            float v10 = acc[f][j][2] + b0, v11 = acc[f][j][3] + b1;
            if (RELU) {
                v00 = fmaxf(v00, 0.f); v01 = fmaxf(v01, 0.f);
                v10 = fmaxf(v10, 0.f); v11 = fmaxf(v11, 0.f);
            }
            if (!SCATTER) {
                if (row0 + rl < cnt) {
                    float* p = Y + ((size_t)e * CAP_ + row0 + rl) * NTOT + n0 + c;
                    ((uint32_t*)p)[0] = f2tf(v00);
                    ((uint32_t*)p)[1] = f2tf(v01);
                }
                if (row0 + rl + 8 < cnt) {
                    float* p = Y + ((size_t)e * CAP_ + row0 + rl + 8) * NTOT + n0 + c;
                    ((uint32_t*)p)[0] = f2tf(v10);
                    ((uint32_t*)p)[1] = f2tf(v11);
                }
            } else {
                int t0 = stok[rl];
                if (t0 >= 0) {
                    float w0 = swt[rl];
                    atomicAdd(Yout + (size_t)t0 * D_OUT_ + n0 + c,     v00 * w0);
                    atomicAdd(Yout + (size_t)t0 * D_OUT_ + n0 + c + 1, v01 * w0);
                }
                int t1 = stok[rl + 8];
                if (t1 >= 0) {
                    float w1 = swt[rl + 8];
                    atomicAdd(Yout + (size_t)t1 * D_OUT_ + n0 + c,     v10 * w1);
                    atomicAdd(Yout + (size_t)t1 * D_OUT_ + n0 + c + 1, v11 * w1);
                }
            }
        }
    }
}

// ---------------- aux outputs ----------------
__global__ void finalize_kernel(float* __restrict__ out) {
    __shared__ float us[E_];
    const int e = threadIdx.x;
    if (e < E_) {
        float u = (float)g_counts[e] / (float)B_;
        us[e] = u;
        out[(size_t)B_ * D_OUT_ + 1 + e] = u;
    }
    __syncthreads();
    if (e == 0) {
        float s = 0.f;
        #pragma unroll
        for (int i = 0; i < E_; ++i) { float d = us[i] - (1.f / E_); s += d * d; }
        out[(size_t)B_ * D_OUT_] = (s / E_) * 0.01f;
    }
}

// ---------------- launch ----------------
extern "C" void kernel_launch(void* const* d_in, const int* in_sizes, int n_in,
                              void* d_out, int out_size) {
    const float* x   = (const float*)d_in[0];
    const float* gW1 = (const float*)d_in[1];
    const float* gb1 = (const float*)d_in[2];
    const float* gW2 = (const float*)d_in[3];
    const float* gb2 = (const float*)d_in[4];
    const float* We1 = (const float*)d_in[5];
    const float* be1 = (const float*)d_in[6];
    const float* We2 = (const float*)d_in[7];
    const float* be2 = (const float*)d_in[8];
    const float* We3 = (const float*)d_in[9];
    const float* be3 = (const float*)d_in[10];
    float* out = (float*)d_out;

    cudaFuncSetAttribute(gating_kernel, cudaFuncAttributeMaxDynamicSharedMemorySize,
                         GATE_SMEM_FLOATS * 4);
    cudaFuncSetAttribute(gemm_mma<256, 512, 1, true,  false>,
                         cudaFuncAttributeMaxDynamicSharedMemorySize, GEMM_DSMEM);
    cudaFuncSetAttribute(gemm_mma<512, 512, 2, true,  false>,
                         cudaFuncAttributeMaxDynamicSharedMemorySize, GEMM_DSMEM);
    cudaFuncSetAttribute(gemm_mma<512, 256, 3, false, true>,
                         cudaFuncAttributeMaxDynamicSharedMemorySize, GEMM_DSMEM);

    zero_kernel<<<512, 256>>>(out);
    transpose_kernel<<<dim3(256 / 32, 512 / 32, E_), 256>>>(We1, 1, 256, 512);
    transpose_kernel<<<dim3(512 / 32, 512 / 32, E_), 256>>>(We2, 2, 512, 512);
    transpose_kernel<<<dim3(512 / 32, 256 / 32, E_), 256>>>(We3, 3, 512, 256);
    gating_kernel<<<256, 256, GATE_SMEM_FLOATS * 4>>>(x, gW1, gb1, gW2, gb2);
    gather_kernel<<<dim3(CAP_ / 64, E_), 256>>>(x);

    gemm_mma<256, 512, 1, true,  false><<<dim3(CAP_ / 128, 4, E_), 128, GEMM_DSMEM>>>(be1, nullptr);
    gemm_mma<512, 512, 2, true,  false><<<dim3(CAP_ / 128, 4, E_), 128, GEMM_DSMEM>>>(be2, nullptr);
    gemm_mma<512, 256, 3, false, true ><<<dim3(CAP_ / 128, 2, E_), 128, GEMM_DSMEM>>>(be3, out);

    finalize_kernel<<<1, 32>>>(out);
}

// round 9
// speedup vs baseline: 1.0021x; 1.0021x over previous
#include <cuda_runtime.h>
#include <stdint.h>
#include <math.h>

#define B_     32768
#define D_IN_  256
#define D_OUT_ 256
#define E_     8
#define H_     512
#define GH_    128
#define CAP_   32768

// ---------------- scratch (static __device__, no allocation) ----------------
__device__ int   g_counts[E_];
__device__ int   g_list[E_ * B_];
__device__ int   g_pos[B_ * 2];                     // token -> (e*CAP+row) x2
__device__ float g_wtk[B_ * 2];                     // token -> combine weights x2
__device__ float g_xg[(size_t)E_ * CAP_ * D_IN_];   // gathered inputs (tf32-rounded)
__device__ float g_h1[(size_t)E_ * CAP_ * H_];      // layer-1 acts; reused as y3 [.][256]
__device__ float g_h2[(size_t)E_ * CAP_ * H_];      // layer-2 acts
__device__ float g_wT1[(size_t)E_ * H_ * D_IN_];    // We1^T tf32
__device__ float g_wT2[(size_t)E_ * H_ * H_];       // We2^T tf32
__device__ float g_wT3[(size_t)E_ * D_OUT_ * H_];   // We3^T tf32

// ---------------- helpers ----------------
__device__ __forceinline__ uint32_t smem_u32(const void* p) {
    uint32_t a;
    asm("{ .reg .u64 t; cvta.to.shared.u64 t, %1; cvt.u32.u64 %0, t; }" : "=r"(a) : "l"(p));
    return a;
}
__device__ __forceinline__ uint32_t f2tf(float x) {
    uint32_t u;
    asm("cvt.rna.tf32.f32 %0, %1;" : "=r"(u) : "f"(x));
    return u;
}
__device__ __forceinline__ void cp16(uint32_t dst, const float* src) {
    asm volatile("cp.async.cg.shared.global [%0], [%1], 16;"
                 :: "r"(dst), "l"(__cvta_generic_to_global(src)) : "memory");
}
#define CP_COMMIT() asm volatile("cp.async.commit_group;" ::: "memory")
#define CP_WAIT1()  asm volatile("cp.async.wait_group 1;" ::: "memory")

__device__ __forceinline__ void ldsm4(uint32_t* r, uint32_t a) {
    asm volatile("ldmatrix.sync.aligned.m8n8.x4.shared.b16 {%0,%1,%2,%3}, [%4];"
                 : "=r"(r[0]), "=r"(r[1]), "=r"(r[2]), "=r"(r[3]) : "r"(a));
}
__device__ __forceinline__ void mma8(float* d, const uint32_t* a, const uint32_t* b) {
    asm volatile(
        "mma.sync.aligned.m16n8k8.row.col.f32.tf32.tf32.f32 "
        "{%0,%1,%2,%3},{%4,%5,%6,%7},{%8,%9},{%0,%1,%2,%3};\n"
        : "+f"(d[0]), "+f"(d[1]), "+f"(d[2]), "+f"(d[3])
        : "r"(a[0]), "r"(a[1]), "r"(a[2]), "r"(a[3]), "r"(b[0]), "r"(b[1]));
}

#define AP 36

// ---------------- zero expert counters ----------------
__global__ void init_counts() {
    if (threadIdx.x < E_) g_counts[threadIdx.x] = 0;
}

// ---------------- gating: fp32-exact MLP -> top2 -> routed lists + positions ----------------
// (proven rounds 1-7; routing decisions must stay fp32 — tf32 gating flips top-2)
#define GATE_SMEM_FLOATS 35224
__global__ void __launch_bounds__(256) gating_kernel(
    const float* __restrict__ x,  const float* __restrict__ gW1,
    const float* __restrict__ gb1, const float* __restrict__ gW2,
    const float* __restrict__ gb2)
{
    extern __shared__ float sm[];
    float* shw  = sm;            // [128][260] transposed gW1
    float* xs   = sm + 33280;    // [2][256]
    float* hid  = sm + 33792;    // [2][128]
    float* b1s  = sm + 34048;    // [128]
    float* w2s  = sm + 34176;    // [128*8]
    float* b2s  = sm + 35200;    // [8]
    float* logt = sm + 35208;    // [16]

    const int tid = threadIdx.x;
    for (int idx = tid; idx < 256 * 128; idx += 256) {
        int i = idx >> 7, j = idx & 127;
        shw[j * 260 + i] = gW1[idx];
    }
    if (tid < 128) b1s[tid] = gb1[tid];
    for (int idx = tid; idx < 128 * 8; idx += 256) w2s[idx] = gW2[idx];
    if (tid < 8) b2s[tid] = gb2[tid];
    __syncthreads();

    const int j    = tid & 127;
    const int half = tid >> 7;
    for (int p = 0; p < 64; ++p) {
        const int tbase = blockIdx.x * 128 + p * 2;
        const float* xr = x + (size_t)tbase * D_IN_;
        xs[tid]       = xr[tid];
        xs[tid + 256] = xr[tid + 256];
        __syncthreads();

        float acc = 0.f;
        const float4* wr4 = (const float4*)(shw + j * 260);
        const float4* xr4 = (const float4*)(xs + half * 256);
        #pragma unroll
        for (int i4 = 0; i4 < 64; ++i4) {
            float4 w = wr4[i4];
            float4 v = xr4[i4];
            acc = fmaf(w.x, v.x, fmaf(w.y, v.y, fmaf(w.z, v.z, fmaf(w.w, v.w, acc))));
        }
        hid[half * 128 + j] = fmaxf(acc + b1s[j], 0.f);
        __syncthreads();

        if (j < 8) {
            float a = b2s[j];
            const float* hrow = hid + half * 128;
            #pragma unroll 8
            for (int h = 0; h < 128; ++h) a = fmaf(hrow[h], w2s[h * 8 + j], a);
            logt[half * 8 + j] = a;
        }
        __syncthreads();

        if (j == 0) {
            float l[8];
            #pragma unroll
            for (int q = 0; q < 8; ++q) l[q] = logt[half * 8 + q];
            int i1 = 0; float m1 = l[0];
            #pragma unroll
            for (int q = 1; q < 8; ++q) if (l[q] > m1) { m1 = l[q]; i1 = q; }
            int i2 = -1; float m2 = -1e30f;
            #pragma unroll
            for (int q = 0; q < 8; ++q) if (q != i1 && l[q] > m2) { m2 = l[q]; i2 = q; }
            const int t = tbase + half;
            const float ex  = expf(m2 - m1);
            const float den = 1.f + ex;
            int p1 = atomicAdd(&g_counts[i1], 1);
            g_list[i1 * B_ + p1] = t;
            int p2 = atomicAdd(&g_counts[i2], 1);
            g_list[i2 * B_ + p2] = t;
            g_pos[t * 2]     = i1 * CAP_ + p1;
            g_pos[t * 2 + 1] = i2 * CAP_ + p2;
            g_wtk[t * 2]     = 1.f / den;
            g_wtk[t * 2 + 1] = ex / den;
        }
        __syncthreads();
    }
}

// ---------------- gather x rows (tf32-rounded) ----------------
__global__ void __launch_bounds__(256) gather_kernel(const float* __restrict__ x) {
    const int e = blockIdx.y;
    const int n = g_counts[e];
    const int row0 = blockIdx.x * 64;
    if (row0 >= n) return;
    for (int v = threadIdx.x; v < 64 * 64; v += 256) {
        int r = row0 + (v >> 6);
        if (r < n) {
            int t = g_list[e * B_ + r];
            float4 s = ((const float4*)(x + (size_t)t * D_IN_))[v & 63];
            uint4 u;
            u.x = f2tf(s.x); u.y = f2tf(s.y); u.z = f2tf(s.z); u.w = f2tf(s.w);
            ((uint4*)(g_xg + ((size_t)e * CAP_ + r) * D_IN_))[v & 63] = u;
        }
    }
}

// ---------------- expert weight transpose + tf32 round ----------------
__global__ void __launch_bounds__(256) transpose_kernel(const float* __restrict__ in, int sel,
                                                        int K, int N) {
    __shared__ float t[32][33];
    float* out = (sel == 1) ? g_wT1 : (sel == 2) ? g_wT2 : g_wT3;
    const int e = blockIdx.z;
    const int k0 = blockIdx.x * 32, n0 = blockIdx.y * 32;
    const float* I = in + (size_t)e * K * N;
    float* O = out + (size_t)e * K * N;
    const int tx = threadIdx.x & 31, ty = threadIdx.x >> 5;
    #pragma unroll
    for (int p = 0; p < 32; p += 8)
        t[ty + p][tx] = I[(size_t)(k0 + ty + p) * N + n0 + tx];
    __syncthreads();
    #pragma unroll
    for (int p = 0; p < 32; p += 8)
        O[(size_t)(n0 + ty + p) * K + k0 + tx] = __uint_as_float(f2tf(t[tx][ty + p]));
}

// ---------------- tf32 mma.sync GEMM (proven pipeline; n-tile fast for L2 A reuse) ----------------
#define STG_BYTES   18432
#define STAGE_BYTES 36864
#define GEMM_DSMEM  110592

template<int K, int NTOT, int STAGE, bool RELU, bool TFROUND>
__global__ void __launch_bounds__(128, 2) gemm_mma(const float* __restrict__ bias)
{
    const int e = blockIdx.z;
    const int cnt = g_counts[e];
    const int row0 = blockIdx.y * 128;     // y = row tile
    if (row0 >= cnt) return;
    const int n0 = blockIdx.x * 128;       // x = n tile (fast-varying -> A L2 reuse)

    extern __shared__ float dsm[];
    const uint32_t smBase = smem_u32(dsm);

    const int tid = threadIdx.x;
    const int lid = tid & 31, wid = tid >> 5;
    const int g = lid >> 2, tg = lid & 3;
    const int wm = wid >> 1, wn = wid & 1;
    const int mb = wm * 64,  nb = wn * 64;

    const float* A  = (STAGE == 1) ? g_xg  : (STAGE == 2) ? g_h1 : g_h2;
    const float* Wt = (STAGE == 1) ? g_wT1 : (STAGE == 2) ? g_wT2 : g_wT3;
    float* Y = (STAGE == 1) ? g_h1 : (STAGE == 2) ? g_h2 : g_h1;   // stage3: y rows [.][256]
    const float* Ab = A  + ((size_t)e * CAP_ + row0) * K;
    const float* Bb = Wt + ((size_t)e * NTOT + n0) * K;

    const int lane_row = (lid & 7) + (((lid >> 3) & 1) << 3);
    const int lane_k   = (lid >> 4) * 4;
    uint32_t aAddr[4], bAddr[4];
    #pragma unroll
    for (int f = 0; f < 4; ++f)
        aAddr[f] = smBase + ((mb + f * 16 + lane_row) * AP + lane_k) * 4;
    {
        const int grp = lid >> 3;
        #pragma unroll
        for (int p = 0; p < 4; ++p) {
            const int n_loc = nb + (2 * p + (grp >> 1)) * 8 + (lid & 7);
            const int kcol  = (grp & 1) * 4;
            bAddr[p] = smBase + STG_BYTES + (n_loc * AP + kcol) * 4;
        }
    }

    float acc[4][8][4];
    #pragma unroll
    for (int f = 0; f < 4; ++f)
        #pragma unroll
        for (int j = 0; j < 8; ++j)
            #pragma unroll
            for (int q = 0; q < 4; ++q) acc[f][j][q] = 0.f;

    auto stage_copy = [&](int buf, int kt) {
        const uint32_t sb = smBase + buf * STAGE_BYTES;
        const int k0 = kt * 32;
        #pragma unroll
        for (int q = 0; q < 8; ++q) {
            const int c = q * 128 + tid;
            const int r = c >> 3, gg = (c & 7) * 4;
            const uint32_t doff = (r * AP + gg) * 4;
            cp16(sb + doff,             Ab + (size_t)r * K + k0 + gg);
            cp16(sb + STG_BYTES + doff, Bb + (size_t)r * K + k0 + gg);
        }
    };

    constexpr int KT = K / 32;
    stage_copy(0, 0); CP_COMMIT();
    stage_copy(1, 1); CP_COMMIT();
    for (int kt = 0; kt < KT; ++kt) {
        CP_WAIT1();
        __syncthreads();

        const uint32_t so = (kt % 3) * STAGE_BYTES;
        #pragma unroll
        for (int kk = 0; kk < 32; kk += 8) {
            uint32_t af[4][4], bf[8][2];
            #pragma unroll
            for (int f = 0; f < 4; ++f) ldsm4(af[f], aAddr[f] + so + kk * 4);
            #pragma unroll
            for (int p = 0; p < 4; ++p) {
                uint32_t bq[4];
                ldsm4(bq, bAddr[p] + so + kk * 4);
                bf[2 * p][0] = bq[0]; bf[2 * p][1] = bq[1];
                bf[2 * p + 1][0] = bq[2]; bf[2 * p + 1][1] = bq[3];
            }
            #pragma unroll
            for (int f = 0; f < 4; ++f)
                #pragma unroll
                for (int j = 0; j < 8; ++j)
                    mma8(acc[f][j], af[f], bf[j]);
        }
        __syncthreads();
        if (kt + 2 < KT) stage_copy((kt + 2) % 3, kt + 2);
        CP_COMMIT();
    }

    // ---------------- epilogue: plain stores (no atomics) ----------------
    const float* Bbias = bias + e * NTOT + n0;
    #pragma unroll
    for (int f = 0; f < 4; ++f) {
        const int rl = mb + f * 16 + g;
        #pragma unroll
        for (int j = 0; j < 8; ++j) {
            const int c = nb + j * 8 + 2 * tg;
            const float b0 = Bbias[c], b1 = Bbias[c + 1];
            float v00 = acc[f][j][0] + b0, v01 = acc[f][j][1] + b1;
            float v10 = acc[f][j][2] + b0, v11 = acc[f][j][3] + b1;
            if (RELU) {
                v00 = fmaxf(v00, 0.f); v01 = fmaxf(v01, 0.f);
                v10 = fmaxf(v10, 0.f); v11 = fmaxf(v11, 0.f);
            }
            if (row0 + rl < cnt) {
                float* p = Y + ((size_t)e * CAP_ + row0 + rl) * NTOT + n0 + c;
                if (TFROUND) { ((uint32_t*)p)[0] = f2tf(v00); ((uint32_t*)p)[1] = f2tf(v01); }
                else         { p[0] = v00; p[1] = v01; }
            }
            if (row0 + rl + 8 < cnt) {
                float* p = Y + ((size_t)e * CAP_ + row0 + rl + 8) * NTOT + n0 + c;
                if (TFROUND) { ((uint32_t*)p)[0] = f2tf(v10); ((uint32_t*)p)[1] = f2tf(v11); }
                else         { p[0] = v10; p[1] = v11; }
            }
        }
    }
}

// ---------------- combine: out[t] = w1*y[p1] + w2*y[p2] ----------------
__global__ void __launch_bounds__(256) combine_kernel(float* __restrict__ out) {
    const int idx = blockIdx.x * blockDim.x + threadIdx.x;    // B_*64 threads
    const int t = idx >> 6, q = idx & 63;
    const int p0 = g_pos[t * 2], p1 = g_pos[t * 2 + 1];
    const float w0 = g_wtk[t * 2], w1 = g_wtk[t * 2 + 1];
    const float4 a = ((const float4*)g_h1)[(size_t)p0 * 64 + q];
    const float4 b = ((const float4*)g_h1)[(size_t)p1 * 64 + q];
    float4 o;
    o.x = w0 * a.x + w1 * b.x;
    o.y = w0 * a.y + w1 * b.y;
    o.z = w0 * a.z + w1 * b.z;
    o.w = w0 * a.w + w1 * b.w;
    ((float4*)out)[(size_t)t * 64 + q] = o;
}

// ---------------- aux outputs ----------------
__global__ void finalize_kernel(float* __restrict__ out) {
    __shared__ float us[E_];
    const int e = threadIdx.x;
    if (e < E_) {
        float u = (float)g_counts[e] / (float)B_;
        us[e] = u;
        out[(size_t)B_ * D_OUT_ + 1 + e] = u;
    }
    __syncthreads();
    if (e == 0) {
        float s = 0.f;
        #pragma unroll
        for (int i = 0; i < E_; ++i) { float d = us[i] - (1.f / E_); s += d * d; }
        out[(size_t)B_ * D_OUT_] = (s / E_) * 0.01f;
    }
}

// ---------------- launch ----------------
extern "C" void kernel_launch(void* const* d_in, const int* in_sizes, int n_in,
                              void* d_out, int out_size) {
    const float* x   = (const float*)d_in[0];
    const float* gW1 = (const float*)d_in[1];
    const float* gb1 = (const float*)d_in[2];
    const float* gW2 = (const float*)d_in[3];
    const float* gb2 = (const float*)d_in[4];
    const float* We1 = (const float*)d_in[5];
    const float* be1 = (const float*)d_in[6];
    const float* We2 = (const float*)d_in[7];
    const float* be2 = (const float*)d_in[8];
    const float* We3 = (const float*)d_in[9];
    const float* be3 = (const float*)d_in[10];
    float* out = (float*)d_out;

    cudaFuncSetAttribute(gating_kernel, cudaFuncAttributeMaxDynamicSharedMemorySize,
                         GATE_SMEM_FLOATS * 4);
    cudaFuncSetAttribute(gemm_mma<256, 512, 1, true,  true>,
                         cudaFuncAttributeMaxDynamicSharedMemorySize, GEMM_DSMEM);
    cudaFuncSetAttribute(gemm_mma<512, 512, 2, true,  true>,
                         cudaFuncAttributeMaxDynamicSharedMemorySize, GEMM_DSMEM);
    cudaFuncSetAttribute(gemm_mma<512, 256, 3, false, false>,
                         cudaFuncAttributeMaxDynamicSharedMemorySize, GEMM_DSMEM);

    init_counts<<<1, 32>>>();
    transpose_kernel<<<dim3(8,  16, E_), 256>>>(We1, 1, 256, 512);
    transpose_kernel<<<dim3(16, 16, E_), 256>>>(We2, 2, 512, 512);
    transpose_kernel<<<dim3(16, 8,  E_), 256>>>(We3, 3, 512, 256);
    gating_kernel<<<256, 256, GATE_SMEM_FLOATS * 4>>>(x, gW1, gb1, gW2, gb2);
    gather_kernel<<<dim3(CAP_ / 64, E_), 256>>>(x);

    gemm_mma<256, 512, 1, true,  true ><<<dim3(4, CAP_ / 128, E_), 128, GEMM_DSMEM>>>(be1);
    gemm_mma<512, 512, 2, true,  true ><<<dim3(4, CAP_ / 128, E_), 128, GEMM_DSMEM>>>(be2);
    gemm_mma<512, 256, 3, false, false><<<dim3(2, CAP_ / 128, E_), 128, GEMM_DSMEM>>>(be3);

    combine_kernel<<<B_ * 64 / 256, 256>>>(out);
    finalize_kernel<<<1, 32>>>(out);
}

// round 10
// speedup vs baseline: 1.3708x; 1.3679x over previous
#include <cuda_runtime.h>
#include <stdint.h>
#include <math.h>

#define B_     32768
#define D_IN_  256
#define D_OUT_ 256
#define E_     8
#define H_     512
#define GH_    128
#define CAP_   32768

// ---------------- scratch (static __device__, no allocation) ----------------
__device__ int   g_counts[E_];
__device__ int   g_list[E_ * B_];
__device__ int   g_pos[B_ * 2];                     // token -> (e*CAP+row) x2
__device__ float g_wtk[B_ * 2];                     // token -> combine weights x2
__device__ float g_xg[(size_t)E_ * CAP_ * D_IN_];   // gathered inputs (tf32-rounded)
__device__ float g_h1[(size_t)E_ * CAP_ * H_];      // layer-1 acts; reused as y3 [.][256]
__device__ float g_h2[(size_t)E_ * CAP_ * H_];      // layer-2 acts
__device__ float g_wT1[(size_t)E_ * H_ * D_IN_];    // We1^T tf32
__device__ float g_wT2[(size_t)E_ * H_ * H_];       // We2^T tf32
__device__ float g_wT3[(size_t)E_ * D_OUT_ * H_];   // We3^T tf32

// ---------------- helpers ----------------
__device__ __forceinline__ uint32_t smem_u32(const void* p) {
    uint32_t a;
    asm("{ .reg .u64 t; cvta.to.shared.u64 t, %1; cvt.u32.u64 %0, t; }" : "=r"(a) : "l"(p));
    return a;
}
__device__ __forceinline__ uint32_t f2tf(float x) {
    uint32_t u;
    asm("cvt.rna.tf32.f32 %0, %1;" : "=r"(u) : "f"(x));
    return u;
}
__device__ __forceinline__ void cp16(uint32_t dst, const float* src) {
    asm volatile("cp.async.cg.shared.global [%0], [%1], 16;"
                 :: "r"(dst), "l"(__cvta_generic_to_global(src)) : "memory");
}
#define CP_COMMIT() asm volatile("cp.async.commit_group;" ::: "memory")
#define CP_WAIT1()  asm volatile("cp.async.wait_group 1;" ::: "memory")

__device__ __forceinline__ void ldsm4(uint32_t* r, uint32_t a) {
    asm volatile("ldmatrix.sync.aligned.m8n8.x4.shared.b16 {%0,%1,%2,%3}, [%4];"
                 : "=r"(r[0]), "=r"(r[1]), "=r"(r[2]), "=r"(r[3]) : "r"(a));
}
__device__ __forceinline__ void mma8(float* d, const uint32_t* a, const uint32_t* b) {
    asm volatile(
        "mma.sync.aligned.m16n8k8.row.col.f32.tf32.tf32.f32 "
        "{%0,%1,%2,%3},{%4,%5,%6,%7},{%8,%9},{%0,%1,%2,%3};\n"
        : "+f"(d[0]), "+f"(d[1]), "+f"(d[2]), "+f"(d[3])
        : "r"(a[0]), "r"(a[1]), "r"(a[2]), "r"(a[3]), "r"(b[0]), "r"(b[1]));
}

#define AP 36

// ---------------- zero expert counters ----------------
__global__ void init_counts() {
    if (threadIdx.x < E_) g_counts[threadIdx.x] = 0;
}

// ---------------- gating: fp32-exact MLP (ILP-4, math identical to r1-r9) ----------------
// 8 tokens per iteration; each thread owns hidden unit j for 4 tokens.
// Per-dot-product fmaf nesting identical to proven kernel -> routing bit-identical.
#define GATE_SMEM_FLOATS 37640
__global__ void __launch_bounds__(256) gating_kernel(
    const float* __restrict__ x,  const float* __restrict__ gW1,
    const float* __restrict__ gb1, const float* __restrict__ gW2,
    const float* __restrict__ gb2)
{
    extern __shared__ float sm[];
    float* shw  = sm;            // [128][260] transposed gW1 : 33280
    float* xs   = sm + 33280;    // [8][256]                  : 2048
    float* hid  = sm + 35328;    // [8][132] padded           : 1056
    float* b1s  = sm + 36384;    // [128]
    float* w2s  = sm + 36512;    // [128*8]
    float* b2s  = sm + 37536;    // [8]
    float* logt = sm + 37544;    // [64]

    const int tid = threadIdx.x;
    for (int idx = tid; idx < 256 * 128; idx += 256) {
        int i = idx >> 7, j = idx & 127;
        shw[j * 260 + i] = gW1[idx];
    }
    if (tid < 128) b1s[tid] = gb1[tid];
    for (int idx = tid; idx < 128 * 8; idx += 256) w2s[idx] = gW2[idx];
    if (tid < 8) b2s[tid] = gb2[tid];
    __syncthreads();

    const int j   = tid & 127;
    const int grp = tid >> 7;            // 0..1 -> tokens grp*4 .. grp*4+3
    for (int p = 0; p < 16; ++p) {
        const int tbase = blockIdx.x * 128 + p * 8;
        {   // load 8 tokens x 256 floats (512 float4 by 256 threads)
            const float4* xsrc = (const float4*)(x + (size_t)tbase * D_IN_);
            float4* xd = (float4*)xs;
            xd[tid]       = xsrc[tid];
            xd[tid + 256] = xsrc[tid + 256];
        }
        __syncthreads();

        // hidden: 4 independent chains per thread, identical per-chain order
        {
            float a0 = 0.f, a1 = 0.f, a2 = 0.f, a3 = 0.f;
            const float4* wr4 = (const float4*)(shw + j * 260);
            const float4* x0 = (const float4*)(xs + (grp * 4 + 0) * 256);
            const float4* x1 = (const float4*)(xs + (grp * 4 + 1) * 256);
            const float4* x2 = (const float4*)(xs + (grp * 4 + 2) * 256);
            const float4* x3 = (const float4*)(xs + (grp * 4 + 3) * 256);
            #pragma unroll
            for (int i4 = 0; i4 < 64; ++i4) {
                float4 w = wr4[i4];
                float4 v0 = x0[i4], v1 = x1[i4], v2 = x2[i4], v3 = x3[i4];
                a0 = fmaf(w.x, v0.x, fmaf(w.y, v0.y, fmaf(w.z, v0.z, fmaf(w.w, v0.w, a0))));
                a1 = fmaf(w.x, v1.x, fmaf(w.y, v1.y, fmaf(w.z, v1.z, fmaf(w.w, v1.w, a1))));
                a2 = fmaf(w.x, v2.x, fmaf(w.y, v2.y, fmaf(w.z, v2.z, fmaf(w.w, v2.w, a2))));
                a3 = fmaf(w.x, v3.x, fmaf(w.y, v3.y, fmaf(w.z, v3.z, fmaf(w.w, v3.w, a3))));
            }
            const float b = b1s[j];
            hid[(grp * 4 + 0) * 132 + j] = fmaxf(a0 + b, 0.f);
            hid[(grp * 4 + 1) * 132 + j] = fmaxf(a1 + b, 0.f);
            hid[(grp * 4 + 2) * 132 + j] = fmaxf(a2 + b, 0.f);
            hid[(grp * 4 + 3) * 132 + j] = fmaxf(a3 + b, 0.f);
        }
        __syncthreads();

        // logits: 64 threads, one per (token, expert), identical serial order
        if (tid < 64) {
            const int tok = tid >> 3, ee = tid & 7;
            float a = b2s[ee];
            const float* hrow = hid + tok * 132;
            #pragma unroll 8
            for (int h = 0; h < 128; ++h) a = fmaf(hrow[h], w2s[h * 8 + ee], a);
            logt[tid] = a;
        }
        __syncthreads();

        // top-2 + routing: 8 threads, one per token (identical selection logic)
        if (tid < 8) {
            float l[8];
            #pragma unroll
            for (int q = 0; q < 8; ++q) l[q] = logt[tid * 8 + q];
            int i1 = 0; float m1 = l[0];
            #pragma unroll
            for (int q = 1; q < 8; ++q) if (l[q] > m1) { m1 = l[q]; i1 = q; }
            int i2 = -1; float m2 = -1e30f;
            #pragma unroll
            for (int q = 0; q < 8; ++q) if (q != i1 && l[q] > m2) { m2 = l[q]; i2 = q; }
            const int t = tbase + tid;
            const float ex  = expf(m2 - m1);
            const float den = 1.f + ex;
            int p1 = atomicAdd(&g_counts[i1], 1);
            g_list[i1 * B_ + p1] = t;
            int p2 = atomicAdd(&g_counts[i2], 1);
            g_list[i2 * B_ + p2] = t;
            g_pos[t * 2]     = i1 * CAP_ + p1;
            g_pos[t * 2 + 1] = i2 * CAP_ + p2;
            g_wtk[t * 2]     = 1.f / den;
            g_wtk[t * 2 + 1] = ex / den;
        }
        __syncthreads();
    }
}

// ---------------- gather x rows (tf32-rounded) ----------------
__global__ void __launch_bounds__(256) gather_kernel(const float* __restrict__ x) {
    const int e = blockIdx.y;
    const int n = g_counts[e];
    const int row0 = blockIdx.x * 64;
    if (row0 >= n) return;
    for (int v = threadIdx.x; v < 64 * 64; v += 256) {
        int r = row0 + (v >> 6);
        if (r < n) {
            int t = g_list[e * B_ + r];
            float4 s = ((const float4*)(x + (size_t)t * D_IN_))[v & 63];
            uint4 u;
            u.x = f2tf(s.x); u.y = f2tf(s.y); u.z = f2tf(s.z); u.w = f2tf(s.w);
            ((uint4*)(g_xg + ((size_t)e * CAP_ + r) * D_IN_))[v & 63] = u;
        }
    }
}

// ---------------- expert weight transpose + tf32 round ----------------
__global__ void __launch_bounds__(256) transpose_kernel(const float* __restrict__ in, int sel,
                                                        int K, int N) {
    __shared__ float t[32][33];
    float* out = (sel == 1) ? g_wT1 : (sel == 2) ? g_wT2 : g_wT3;
    const int e = blockIdx.z;
    const int k0 = blockIdx.x * 32, n0 = blockIdx.y * 32;
    const float* I = in + (size_t)e * K * N;
    float* O = out + (size_t)e * K * N;
    const int tx = threadIdx.x & 31, ty = threadIdx.x >> 5;
    #pragma unroll
    for (int p = 0; p < 32; p += 8)
        t[ty + p][tx] = I[(size_t)(k0 + ty + p) * N + n0 + tx];
    __syncthreads();
    #pragma unroll
    for (int p = 0; p < 32; p += 8)
        O[(size_t)(n0 + ty + p) * K + k0 + tx] = __uint_as_float(f2tf(t[tx][ty + p]));
}

// ---------------- tf32 mma.sync GEMM: single barrier per k-tile, copy-before-compute ----------------
#define STG_BYTES   18432
#define STAGE_BYTES 36864
#define GEMM_DSMEM  110592

template<int K, int NTOT, int STAGE, bool RELU, bool TFROUND>
__global__ void __launch_bounds__(128, 2) gemm_mma(const float* __restrict__ bias)
{
    const int e = blockIdx.z;
    const int cnt = g_counts[e];
    const int row0 = blockIdx.y * 128;     // y = row tile
    if (row0 >= cnt) return;
    const int n0 = blockIdx.x * 128;       // x = n tile (fast-varying -> A L2 reuse)

    extern __shared__ float dsm[];
    const uint32_t smBase = smem_u32(dsm);

    const int tid = threadIdx.x;
    const int lid = tid & 31, wid = tid >> 5;
    const int g = lid >> 2, tg = lid & 3;
    const int wm = wid >> 1, wn = wid & 1;
    const int mb = wm * 64,  nb = wn * 64;

    const float* A  = (STAGE == 1) ? g_xg  : (STAGE == 2) ? g_h1 : g_h2;
    const float* Wt = (STAGE == 1) ? g_wT1 : (STAGE == 2) ? g_wT2 : g_wT3;
    float* Y = (STAGE == 1) ? g_h1 : (STAGE == 2) ? g_h2 : g_h1;   // stage3: y rows [.][256]
    const float* Ab = A  + ((size_t)e * CAP_ + row0) * K;
    const float* Bb = Wt + ((size_t)e * NTOT + n0) * K;

    const int lane_row = (lid & 7) + (((lid >> 3) & 1) << 3);
    const int lane_k   = (lid >> 4) * 4;
    uint32_t aAddr[4], bAddr[4];
    #pragma unroll
    for (int f = 0; f < 4; ++f)
        aAddr[f] = smBase + ((mb + f * 16 + lane_row) * AP + lane_k) * 4;
    {
        const int grp = lid >> 3;
        #pragma unroll
        for (int p = 0; p < 4; ++p) {
            const int n_loc = nb + (2 * p + (grp >> 1)) * 8 + (lid & 7);
            const int kcol  = (grp & 1) * 4;
            bAddr[p] = smBase + STG_BYTES + (n_loc * AP + kcol) * 4;
        }
    }

    float acc[4][8][4];
    #pragma unroll
    for (int f = 0; f < 4; ++f)
        #pragma unroll
        for (int j = 0; j < 8; ++j)
            #pragma unroll
            for (int q = 0; q < 4; ++q) acc[f][j][q] = 0.f;

    auto stage_copy = [&](int buf, int kt) {
        const uint32_t sb = smBase + buf * STAGE_BYTES;
        const int k0 = kt * 32;
        #pragma unroll
        for (int q = 0; q < 8; ++q) {
            const int c = q * 128 + tid;
            const int r = c >> 3, gg = (c & 7) * 4;
            const uint32_t doff = (r * AP + gg) * 4;
            cp16(sb + doff,             Ab + (size_t)r * K + k0 + gg);
            cp16(sb + STG_BYTES + doff, Bb + (size_t)r * K + k0 + gg);
        }
    };

    constexpr int KT = K / 32;
    stage_copy(0, 0); CP_COMMIT();
    stage_copy(1, 1); CP_COMMIT();
    for (int kt = 0; kt < KT; ++kt) {
        CP_WAIT1();                       // stage kt resident (group kt complete)
        __syncthreads();                  // all warps done reading stage (kt-1)%3
        if (kt + 2 < KT) stage_copy((kt + 2) % 3, kt + 2);   // refill freed stage
        CP_COMMIT();                      // unconditional: group arithmetic exact

        const uint32_t so = (kt % 3) * STAGE_BYTES;
        #pragma unroll
        for (int kk = 0; kk < 32; kk += 8) {
            uint32_t af[4][4], bf[8][2];
            #pragma unroll
            for (int f = 0; f < 4; ++f) ldsm4(af[f], aAddr[f] + so + kk * 4);
            #pragma unroll
            for (int p = 0; p < 4; ++p) {
                uint32_t bq[4];
                ldsm4(bq, bAddr[p] + so + kk * 4);
                bf[2 * p][0] = bq[0]; bf[2 * p][1] = bq[1];
                bf[2 * p + 1][0] = bq[2]; bf[2 * p + 1][1] = bq[3];
            }
            #pragma unroll
            for (int f = 0; f < 4; ++f)
                #pragma unroll
                for (int j = 0; j < 8; ++j)
                    mma8(acc[f][j], af[f], bf[j]);
        }
    }

    // ---------------- epilogue: plain stores (no atomics) ----------------
    const float* Bbias = bias + e * NTOT + n0;
    #pragma unroll
    for (int f = 0; f < 4; ++f) {
        const int rl = mb + f * 16 + g;
        #pragma unroll
        for (int j = 0; j < 8; ++j) {
            const int c = nb + j * 8 + 2 * tg;
            const float b0 = Bbias[c], b1 = Bbias[c + 1];
            float v00 = acc[f][j][0] + b0, v01 = acc[f][j][1] + b1;
            float v10 = acc[f][j][2] + b0, v11 = acc[f][j][3] + b1;
            if (RELU) {
                v00 = fmaxf(v00, 0.f); v01 = fmaxf(v01, 0.f);
                v10 = fmaxf(v10, 0.f); v11 = fmaxf(v11, 0.f);
            }
            if (row0 + rl < cnt) {
                float* p = Y + ((size_t)e * CAP_ + row0 + rl) * NTOT + n0 + c;
                if (TFROUND) { ((uint32_t*)p)[0] = f2tf(v00); ((uint32_t*)p)[1] = f2tf(v01); }
                else         { p[0] = v00; p[1] = v01; }
            }
            if (row0 + rl + 8 < cnt) {
                float* p = Y + ((size_t)e * CAP_ + row0 + rl + 8) * NTOT + n0 + c;
                if (TFROUND) { ((uint32_t*)p)[0] = f2tf(v10); ((uint32_t*)p)[1] = f2tf(v11); }
                else         { p[0] = v10; p[1] = v11; }
            }
        }
    }
}

// ---------------- combine: out[t] = w1*y[p1] + w2*y[p2] ----------------
__global__ void __launch_bounds__(256) combine_kernel(float* __restrict__ out) {
    const int idx = blockIdx.x * blockDim.x + threadIdx.x;    // B_*64 threads
    const int t = idx >> 6, q = idx & 63;
    const int p0 = g_pos[t * 2], p1 = g_pos[t * 2 + 1];
    const float w0 = g_wtk[t * 2], w1 = g_wtk[t * 2 + 1];
    const float4 a = ((const float4*)g_h1)[(size_t)p0 * 64 + q];
    const float4 b = ((const float4*)g_h1)[(size_t)p1 * 64 + q];
    float4 o;
    o.x = w0 * a.x + w1 * b.x;
    o.y = w0 * a.y + w1 * b.y;
    o.z = w0 * a.z + w1 * b.z;
    o.w = w0 * a.w + w1 * b.w;
    ((float4*)out)[(size_t)t * 64 + q] = o;
}

// ---------------- aux outputs ----------------
__global__ void finalize_kernel(float* __restrict__ out) {
    __shared__ float us[E_];
    const int e = threadIdx.x;
    if (e < E_) {
        float u = (float)g_counts[e] / (float)B_;
        us[e] = u;
        out[(size_t)B_ * D_OUT_ + 1 + e] = u;
    }
    __syncthreads();
    if (e == 0) {
        float s = 0.f;
        #pragma unroll
        for (int i = 0; i < E_; ++i) { float d = us[i] - (1.f / E_); s += d * d; }
        out[(size_t)B_ * D_OUT_] = (s / E_) * 0.01f;
    }
}

// ---------------- launch (gating placed at launch slot 4 for ncu capture) ----------------
extern "C" void kernel_launch(void* const* d_in, const int* in_sizes, int n_in,
                              void* d_out, int out_size) {
    const float* x   = (const float*)d_in[0];
    const float* gW1 = (const float*)d_in[1];
    const float* gb1 = (const float*)d_in[2];
    const float* gW2 = (const float*)d_in[3];
    const float* gb2 = (const float*)d_in[4];
    const float* We1 = (const float*)d_in[5];
    const float* be1 = (const float*)d_in[6];
    const float* We2 = (const float*)d_in[7];
    const float* be2 = (const float*)d_in[8];
    const float* We3 = (const float*)d_in[9];
    const float* be3 = (const float*)d_in[10];
    float* out = (float*)d_out;

    cudaFuncSetAttribute(gating_kernel, cudaFuncAttributeMaxDynamicSharedMemorySize,
                         GATE_SMEM_FLOATS * 4);
    cudaFuncSetAttribute(gemm_mma<256, 512, 1, true,  true>,
                         cudaFuncAttributeMaxDynamicSharedMemorySize, GEMM_DSMEM);
    cudaFuncSetAttribute(gemm_mma<512, 512, 2, true,  true>,
                         cudaFuncAttributeMaxDynamicSharedMemorySize, GEMM_DSMEM);
    cudaFuncSetAttribute(gemm_mma<512, 256, 3, false, false>,
                         cudaFuncAttributeMaxDynamicSharedMemorySize, GEMM_DSMEM);

    init_counts<<<1, 32>>>();                                        // 1
    transpose_kernel<<<dim3(8,  16, E_), 256>>>(We1, 1, 256, 512);   // 2
    transpose_kernel<<<dim3(16, 16, E_), 256>>>(We2, 2, 512, 512);   // 3
    gating_kernel<<<256, 256, GATE_SMEM_FLOATS * 4>>>(x, gW1, gb1, gW2, gb2); // 4 <- profiled
    transpose_kernel<<<dim3(16, 8,  E_), 256>>>(We3, 3, 512, 256);   // 5
    gather_kernel<<<dim3(CAP_ / 64, E_), 256>>>(x);                  // 6

    gemm_mma<256, 512, 1, true,  true ><<<dim3(4, CAP_ / 128, E_), 128, GEMM_DSMEM>>>(be1);
    gemm_mma<512, 512, 2, true,  true ><<<dim3(4, CAP_ / 128, E_), 128, GEMM_DSMEM>>>(be2);
    gemm_mma<512, 256, 3, false, false><<<dim3(2, CAP_ / 128, E_), 128, GEMM_DSMEM>>>(be3);

    combine_kernel<<<B_ * 64 / 256, 256>>>(out);
    finalize_kernel<<<1, 32>>>(out);
}

// round 11
// speedup vs baseline: 1.7329x; 1.2641x over previous
#include <cuda_runtime.h>
#include <stdint.h>
#include <math.h>

#define B_     32768
#define D_IN_  256
#define D_OUT_ 256
#define E_     8
#define H_     512
#define GH_    128
#define CAP_   32768

// ---------------- scratch (static __device__, no allocation) ----------------
__device__ int   g_counts[E_];
__device__ int   g_list[E_ * B_];
__device__ int   g_pos[B_ * 2];                     // token -> (e*CAP+row) x2
__device__ float g_wtk[B_ * 2];                     // token -> combine weights x2
__device__ float g_xg[(size_t)E_ * CAP_ * D_IN_];   // gathered inputs (tf32-rounded)
__device__ float g_h1[(size_t)E_ * CAP_ * H_];      // layer-1 acts; reused as y3 [.][256]
__device__ float g_h2[(size_t)E_ * CAP_ * H_];      // layer-2 acts
__device__ float g_wT1[(size_t)E_ * H_ * D_IN_];    // We1^T tf32
__device__ float g_wT2[(size_t)E_ * H_ * H_];       // We2^T tf32
__device__ float g_wT3[(size_t)E_ * D_OUT_ * H_];   // We3^T tf32

// ---------------- helpers ----------------
__device__ __forceinline__ uint32_t smem_u32(const void* p) {
    uint32_t a;
    asm("{ .reg .u64 t; cvta.to.shared.u64 t, %1; cvt.u32.u64 %0, t; }" : "=r"(a) : "l"(p));
    return a;
}
__device__ __forceinline__ uint32_t f2tf(float x) {
    uint32_t u;
    asm("cvt.rna.tf32.f32 %0, %1;" : "=r"(u) : "f"(x));
    return u;
}
__device__ __forceinline__ void cp16(uint32_t dst, const float* src) {
    asm volatile("cp.async.cg.shared.global [%0], [%1], 16;"
                 :: "r"(dst), "l"(__cvta_generic_to_global(src)) : "memory");
}
#define CP_COMMIT() asm volatile("cp.async.commit_group;" ::: "memory")
#define CP_WAIT1()  asm volatile("cp.async.wait_group 1;" ::: "memory")

__device__ __forceinline__ void ldsm4(uint32_t* r, uint32_t a) {
    asm volatile("ldmatrix.sync.aligned.m8n8.x4.shared.b16 {%0,%1,%2,%3}, [%4];"
                 : "=r"(r[0]), "=r"(r[1]), "=r"(r[2]), "=r"(r[3]) : "r"(a));
}
__device__ __forceinline__ void mma8(float* d, const uint32_t* a, const uint32_t* b) {
    asm volatile(
        "mma.sync.aligned.m16n8k8.row.col.f32.tf32.tf32.f32 "
        "{%0,%1,%2,%3},{%4,%5,%6,%7},{%8,%9},{%0,%1,%2,%3};\n"
        : "+f"(d[0]), "+f"(d[1]), "+f"(d[2]), "+f"(d[3])
        : "r"(a[0]), "r"(a[1]), "r"(a[2]), "r"(a[3]), "r"(b[0]), "r"(b[1]));
}

#define AP 36

// ---------------- zero expert counters ----------------
__global__ void init_counts() {
    if (threadIdx.x < E_) g_counts[threadIdx.x] = 0;
}

// ---------------- gating: register-tiled fp32 SGEMM, routing math bit-identical ----------------
// 128 tokens x 128 hidden per block, BK=8. Each thread: 8x8 micro-tile split 4+4.
// Per-output fmaf chain order identical to rounds 1-10: k-groups of 4 ascending,
// within-group k descending (kk=3..0). Logits/top-2 identical serial code.
#define GATE_DSMEM (128 * 132 * 4)
__global__ void __launch_bounds__(256, 2) gating_kernel(
    const float* __restrict__ x,  const float* __restrict__ gW1,
    const float* __restrict__ gb1, const float* __restrict__ gW2,
    const float* __restrict__ gb2)
{
    extern __shared__ float dsm[];            // staging As[8][132]+Bs[8][132]; later h[128][132]
    float* As = dsm;                          // [8][132]
    float* Bs = dsm + 8 * 132;                // [8][132]
    __shared__ float b1s[GH_], w2s[GH_ * E_], b2s[E_], logt[128 * E_];

    const int tid = threadIdx.x;
    const int tok0 = blockIdx.x * 128;
    if (tid < GH_) b1s[tid] = gb1[tid];
    for (int i = tid; i < GH_ * E_; i += 256) w2s[i] = gW2[i];
    if (tid < E_) b2s[tid] = gb2[tid];

    const int m_ld = tid & 127, half = tid >> 7;        // As staging coords
    const int kb_ld = tid >> 5, j_ld = (tid & 31) * 4;  // Bs staging coords
    const int tx = tid & 15, ty = tid >> 4;
    const int ma = ty * 4, jb = tx * 4;                 // micro-tile bases (+64 for upper half)

    float acc[8][8];
    #pragma unroll
    for (int i = 0; i < 8; ++i)
        #pragma unroll
        for (int j = 0; j < 8; ++j) acc[i][j] = 0.f;

    for (int kt = 0; kt < 32; ++kt) {
        const int k0 = kt * 8;
        float4 xa = *(const float4*)(x + (size_t)(tok0 + m_ld) * D_IN_ + k0 + half * 4);
        float4 wb = *(const float4*)(gW1 + (size_t)(k0 + kb_ld) * GH_ + j_ld);
        __syncthreads();                     // prior tile fully consumed
        As[(half * 4 + 0) * 132 + m_ld] = xa.x;
        As[(half * 4 + 1) * 132 + m_ld] = xa.y;
        As[(half * 4 + 2) * 132 + m_ld] = xa.z;
        As[(half * 4 + 3) * 132 + m_ld] = xa.w;
        *(float4*)(Bs + kb_ld * 132 + j_ld) = wb;
        __syncthreads();

        #pragma unroll
        for (int g = 0; g < 2; ++g) {
            #pragma unroll
            for (int kk = 3; kk >= 0; --kk) {      // descending within group: matches nesting
                const int k = g * 4 + kk;
                float4 a0 = *(const float4*)(As + k * 132 + ma);
                float4 a1 = *(const float4*)(As + k * 132 + 64 + ma);
                float4 b0 = *(const float4*)(Bs + k * 132 + jb);
                float4 b1 = *(const float4*)(Bs + k * 132 + 64 + jb);
                const float av[8] = {a0.x, a0.y, a0.z, a0.w, a1.x, a1.y, a1.z, a1.w};
                const float bv[8] = {b0.x, b0.y, b0.z, b0.w, b1.x, b1.y, b1.z, b1.w};
                #pragma unroll
                for (int i = 0; i < 8; ++i)
                    #pragma unroll
                    for (int j = 0; j < 8; ++j)
                        acc[i][j] = fmaf(av[i], bv[j], acc[i][j]);
            }
        }
    }
    __syncthreads();                         // staging dead; alias h over it

    // h = relu(acc + b1), to smem [128][132]
    float* hsm = dsm;
    #pragma unroll
    for (int i = 0; i < 8; ++i) {
        const int m = ma + (i & 3) + (i >> 2) * 64;
        #pragma unroll
        for (int j = 0; j < 8; ++j) {
            const int jj = jb + (j & 3) + (j >> 2) * 64;
            hsm[m * 132 + jj] = fmaxf(acc[i][j] + b1s[jj], 0.f);
        }
    }
    __syncthreads();

    // logits: 4 (token,expert) pairs per thread, identical ascending serial chain
    #pragma unroll
    for (int q = 0; q < 4; ++q) {
        const int pid = tid + q * 256;
        const int tok = pid >> 3, ee = pid & 7;
        float a = b2s[ee];
        const float* hrow = hsm + tok * 132;
        #pragma unroll 8
        for (int h = 0; h < 128; ++h) a = fmaf(hrow[h], w2s[h * 8 + ee], a);
        logt[tok * 8 + ee] = a;
    }
    __syncthreads();

    // top-2 + routing (identical selection logic)
    if (tid < 128) {
        float l[8];
        #pragma unroll
        for (int q = 0; q < 8; ++q) l[q] = logt[tid * 8 + q];
        int i1 = 0; float m1 = l[0];
        #pragma unroll
        for (int q = 1; q < 8; ++q) if (l[q] > m1) { m1 = l[q]; i1 = q; }
        int i2 = -1; float m2 = -1e30f;
        #pragma unroll
        for (int q = 0; q < 8; ++q) if (q != i1 && l[q] > m2) { m2 = l[q]; i2 = q; }
        const int t = tok0 + tid;
        const float ex  = expf(m2 - m1);
        const float den = 1.f + ex;
        int p1 = atomicAdd(&g_counts[i1], 1);
        g_list[i1 * B_ + p1] = t;
        int p2 = atomicAdd(&g_counts[i2], 1);
        g_list[i2 * B_ + p2] = t;
        g_pos[t * 2]     = i1 * CAP_ + p1;
        g_pos[t * 2 + 1] = i2 * CAP_ + p2;
        g_wtk[t * 2]     = 1.f / den;
        g_wtk[t * 2 + 1] = ex / den;
    }
}

// ---------------- gather x rows (tf32-rounded) ----------------
__global__ void __launch_bounds__(256) gather_kernel(const float* __restrict__ x) {
    const int e = blockIdx.y;
    const int n = g_counts[e];
    const int row0 = blockIdx.x * 64;
    if (row0 >= n) return;
    for (int v = threadIdx.x; v < 64 * 64; v += 256) {
        int r = row0 + (v >> 6);
        if (r < n) {
            int t = g_list[e * B_ + r];
            float4 s = ((const float4*)(x + (size_t)t * D_IN_))[v & 63];
            uint4 u;
            u.x = f2tf(s.x); u.y = f2tf(s.y); u.z = f2tf(s.z); u.w = f2tf(s.w);
            ((uint4*)(g_xg + ((size_t)e * CAP_ + r) * D_IN_))[v & 63] = u;
        }
    }
}

// ---------------- expert weight transpose + tf32 round ----------------
__global__ void __launch_bounds__(256) transpose_kernel(const float* __restrict__ in, int sel,
                                                        int K, int N) {
    __shared__ float t[32][33];
    float* out = (sel == 1) ? g_wT1 : (sel == 2) ? g_wT2 : g_wT3;
    const int e = blockIdx.z;
    const int k0 = blockIdx.x * 32, n0 = blockIdx.y * 32;
    const float* I = in + (size_t)e * K * N;
    float* O = out + (size_t)e * K * N;
    const int tx = threadIdx.x & 31, ty = threadIdx.x >> 5;
    #pragma unroll
    for (int p = 0; p < 32; p += 8)
        t[ty + p][tx] = I[(size_t)(k0 + ty + p) * N + n0 + tx];
    __syncthreads();
    #pragma unroll
    for (int p = 0; p < 32; p += 8)
        O[(size_t)(n0 + ty + p) * K + k0 + tx] = __uint_as_float(f2tf(t[tx][ty + p]));
}

// ---------------- tf32 mma.sync GEMM (proven r10 pipeline) ----------------
#define STG_BYTES   18432
#define STAGE_BYTES 36864
#define GEMM_DSMEM  110592

template<int K, int NTOT, int STAGE, bool RELU, bool TFROUND>
__global__ void __launch_bounds__(128, 2) gemm_mma(const float* __restrict__ bias)
{
    const int e = blockIdx.z;
    const int cnt = g_counts[e];
    const int row0 = blockIdx.y * 128;     // y = row tile
    if (row0 >= cnt) return;
    const int n0 = blockIdx.x * 128;       // x = n tile (fast-varying -> A L2 reuse)

    extern __shared__ float dsm[];
    const uint32_t smBase = smem_u32(dsm);

    const int tid = threadIdx.x;
    const int lid = tid & 31, wid = tid >> 5;
    const int g = lid >> 2, tg = lid & 3;
    const int wm = wid >> 1, wn = wid & 1;
    const int mb = wm * 64,  nb = wn * 64;

    const float* A  = (STAGE == 1) ? g_xg  : (STAGE == 2) ? g_h1 : g_h2;
    const float* Wt = (STAGE == 1) ? g_wT1 : (STAGE == 2) ? g_wT2 : g_wT3;
    float* Y = (STAGE == 1) ? g_h1 : (STAGE == 2) ? g_h2 : g_h1;   // stage3: y rows [.][256]
    const float* Ab = A  + ((size_t)e * CAP_ + row0) * K;
    const float* Bb = Wt + ((size_t)e * NTOT + n0) * K;

    const int lane_row = (lid & 7) + (((lid >> 3) & 1) << 3);
    const int lane_k   = (lid >> 4) * 4;
    uint32_t aAddr[4], bAddr[4];
    #pragma unroll
    for (int f = 0; f < 4; ++f)
        aAddr[f] = smBase + ((mb + f * 16 + lane_row) * AP + lane_k) * 4;
    {
        const int grp = lid >> 3;
        #pragma unroll
        for (int p = 0; p < 4; ++p) {
            const int n_loc = nb + (2 * p + (grp >> 1)) * 8 + (lid & 7);
            const int kcol  = (grp & 1) * 4;
            bAddr[p] = smBase + STG_BYTES + (n_loc * AP + kcol) * 4;
        }
    }

    float acc[4][8][4];
    #pragma unroll
    for (int f = 0; f < 4; ++f)
        #pragma unroll
        for (int j = 0; j < 8; ++j)
            #pragma unroll
            for (int q = 0; q < 4; ++q) acc[f][j][q] = 0.f;

    auto stage_copy = [&](int buf, int kt) {
        const uint32_t sb = smBase + buf * STAGE_BYTES;
        const int k0 = kt * 32;
        #pragma unroll
        for (int q = 0; q < 8; ++q) {
            const int c = q * 128 + tid;
            const int r = c >> 3, gg = (c & 7) * 4;
            const uint32_t doff = (r * AP + gg) * 4;
            cp16(sb + doff,             Ab + (size_t)r * K + k0 + gg);
            cp16(sb + STG_BYTES + doff, Bb + (size_t)r * K + k0 + gg);
        }
    };

    constexpr int KT = K / 32;
    stage_copy(0, 0); CP_COMMIT();
    stage_copy(1, 1); CP_COMMIT();
    for (int kt = 0; kt < KT; ++kt) {
        CP_WAIT1();                       // stage kt resident (group kt complete)
        __syncthreads();                  // all warps done reading stage (kt-1)%3
        if (kt + 2 < KT) stage_copy((kt + 2) % 3, kt + 2);   // refill freed stage
        CP_COMMIT();                      // unconditional: group arithmetic exact

        const uint32_t so = (kt % 3) * STAGE_BYTES;
        #pragma unroll
        for (int kk = 0; kk < 32; kk += 8) {
            uint32_t af[4][4], bf[8][2];
            #pragma unroll
            for (int f = 0; f < 4; ++f) ldsm4(af[f], aAddr[f] + so + kk * 4);
            #pragma unroll
            for (int p = 0; p < 4; ++p) {
                uint32_t bq[4];
                ldsm4(bq, bAddr[p] + so + kk * 4);
                bf[2 * p][0] = bq[0]; bf[2 * p][1] = bq[1];
                bf[2 * p + 1][0] = bq[2]; bf[2 * p + 1][1] = bq[3];
            }
            #pragma unroll
            for (int f = 0; f < 4; ++f)
                #pragma unroll
                for (int j = 0; j < 8; ++j)
                    mma8(acc[f][j], af[f], bf[j]);
        }
    }

    // ---------------- epilogue: plain stores (no atomics) ----------------
    const float* Bbias = bias + e * NTOT + n0;
    #pragma unroll
    for (int f = 0; f < 4; ++f) {
        const int rl = mb + f * 16 + g;
        #pragma unroll
        for (int j = 0; j < 8; ++j) {
            const int c = nb + j * 8 + 2 * tg;
            const float b0 = Bbias[c], b1 = Bbias[c + 1];
            float v00 = acc[f][j][0] + b0, v01 = acc[f][j][1] + b1;
            float v10 = acc[f][j][2] + b0, v11 = acc[f][j][3] + b1;
            if (RELU) {
                v00 = fmaxf(v00, 0.f); v01 = fmaxf(v01, 0.f);
                v10 = fmaxf(v10, 0.f); v11 = fmaxf(v11, 0.f);
            }
            if (row0 + rl < cnt) {
                float* p = Y + ((size_t)e * CAP_ + row0 + rl) * NTOT + n0 + c;
                if (TFROUND) { ((uint32_t*)p)[0] = f2tf(v00); ((uint32_t*)p)[1] = f2tf(v01); }
                else         { p[0] = v00; p[1] = v01; }
            }
            if (row0 + rl + 8 < cnt) {
                float* p = Y + ((size_t)e * CAP_ + row0 + rl + 8) * NTOT + n0 + c;
                if (TFROUND) { ((uint32_t*)p)[0] = f2tf(v10); ((uint32_t*)p)[1] = f2tf(v11); }
                else         { p[0] = v10; p[1] = v11; }
            }
        }
    }
}

// ---------------- combine: out[t] = w1*y[p1] + w2*y[p2] ----------------
__global__ void __launch_bounds__(256) combine_kernel(float* __restrict__ out) {
    const int idx = blockIdx.x * blockDim.x + threadIdx.x;    // B_*64 threads
    const int t = idx >> 6, q = idx & 63;
    const int p0 = g_pos[t * 2], p1 = g_pos[t * 2 + 1];
    const float w0 = g_wtk[t * 2], w1 = g_wtk[t * 2 + 1];
    const float4 a = ((const float4*)g_h1)[(size_t)p0 * 64 + q];
    const float4 b = ((const float4*)g_h1)[(size_t)p1 * 64 + q];
    float4 o;
    o.x = w0 * a.x + w1 * b.x;
    o.y = w0 * a.y + w1 * b.y;
    o.z = w0 * a.z + w1 * b.z;
    o.w = w0 * a.w + w1 * b.w;
    ((float4*)out)[(size_t)t * 64 + q] = o;
}

// ---------------- aux outputs ----------------
__global__ void finalize_kernel(float* __restrict__ out) {
    __shared__ float us[E_];
    const int e = threadIdx.x;
    if (e < E_) {
        float u = (float)g_counts[e] / (float)B_;
        us[e] = u;
        out[(size_t)B_ * D_OUT_ + 1 + e] = u;
    }
    __syncthreads();
    if (e == 0) {
        float s = 0.f;
        #pragma unroll
        for (int i = 0; i < E_; ++i) { float d = us[i] - (1.f / E_); s += d * d; }
        out[(size_t)B_ * D_OUT_] = (s / E_) * 0.01f;
    }
}

// ---------------- launch (gating at slot 4 for ncu capture) ----------------
extern "C" void kernel_launch(void* const* d_in, const int* in_sizes, int n_in,
                              void* d_out, int out_size) {
    const float* x   = (const float*)d_in[0];
    const float* gW1 = (const float*)d_in[1];
    const float* gb1 = (const float*)d_in[2];
    const float* gW2 = (const float*)d_in[3];
    const float* gb2 = (const float*)d_in[4];
    const float* We1 = (const float*)d_in[5];
    const float* be1 = (const float*)d_in[6];
    const float* We2 = (const float*)d_in[7];
    const float* be2 = (const float*)d_in[8];
    const float* We3 = (const float*)d_in[9];
    const float* be3 = (const float*)d_in[10];
    float* out = (float*)d_out;

    cudaFuncSetAttribute(gating_kernel, cudaFuncAttributeMaxDynamicSharedMemorySize,
                         GATE_DSMEM);
    cudaFuncSetAttribute(gemm_mma<256, 512, 1, true,  true>,
                         cudaFuncAttributeMaxDynamicSharedMemorySize, GEMM_DSMEM);
    cudaFuncSetAttribute(gemm_mma<512, 512, 2, true,  true>,
                         cudaFuncAttributeMaxDynamicSharedMemorySize, GEMM_DSMEM);
    cudaFuncSetAttribute(gemm_mma<512, 256, 3, false, false>,
                         cudaFuncAttributeMaxDynamicSharedMemorySize, GEMM_DSMEM);

    init_counts<<<1, 32>>>();                                        // 1
    transpose_kernel<<<dim3(8,  16, E_), 256>>>(We1, 1, 256, 512);   // 2
    transpose_kernel<<<dim3(16, 16, E_), 256>>>(We2, 2, 512, 512);   // 3
    gating_kernel<<<256, 256, GATE_DSMEM>>>(x, gW1, gb1, gW2, gb2);  // 4 <- profiled
    transpose_kernel<<<dim3(16, 8,  E_), 256>>>(We3, 3, 512, 256);   // 5
    gather_kernel<<<dim3(CAP_ / 64, E_), 256>>>(x);                  // 6

    gemm_mma<256, 512, 1, true,  true ><<<dim3(4, CAP_ / 128, E_), 128, GEMM_DSMEM>>>(be1);
    gemm_mma<512, 512, 2, true,  true ><<<dim3(4, CAP_ / 128, E_), 128, GEMM_DSMEM>>>(be2);
    gemm_mma<512, 256, 3, false, false><<<dim3(2, CAP_ / 128, E_), 128, GEMM_DSMEM>>>(be3);

    combine_kernel<<<B_ * 64 / 256, 256>>>(out);
    finalize_kernel<<<1, 32>>>(out);
}

// round 12
// speedup vs baseline: 1.7904x; 1.0332x over previous
#include <cuda_runtime.h>
#include <stdint.h>
#include <math.h>

#define B_     32768
#define D_IN_  256
#define D_OUT_ 256
#define E_     8
#define H_     512
#define GH_    128
#define CAP_   32768

// ---------------- scratch (static __device__, no allocation) ----------------
__device__ int   g_counts[E_];
__device__ int   g_list[E_ * B_];
__device__ int   g_pos[B_ * 2];                     // token -> (e*CAP+row) x2
__device__ float g_wtk[B_ * 2];                     // token -> combine weights x2
__device__ float g_h1[(size_t)E_ * CAP_ * H_];      // layer-1 acts; reused as y3 [.][256]
__device__ float g_h2[(size_t)E_ * CAP_ * H_];      // layer-2 acts
__device__ float g_wT1[(size_t)E_ * H_ * D_IN_];    // We1^T tf32
__device__ float g_wT2[(size_t)E_ * H_ * H_];       // We2^T tf32
__device__ float g_wT3[(size_t)E_ * D_OUT_ * H_];   // We3^T tf32

// ---------------- helpers ----------------
__device__ __forceinline__ uint32_t smem_u32(const void* p) {
    uint32_t a;
    asm("{ .reg .u64 t; cvta.to.shared.u64 t, %1; cvt.u32.u64 %0, t; }" : "=r"(a) : "l"(p));
    return a;
}
__device__ __forceinline__ uint32_t f2tf(float x) {
    uint32_t u;
    asm("cvt.rna.tf32.f32 %0, %1;" : "=r"(u) : "f"(x));
    return u;
}
__device__ __forceinline__ void cp16(uint32_t dst, const float* src) {
    asm volatile("cp.async.cg.shared.global [%0], [%1], 16;"
                 :: "r"(dst), "l"(__cvta_generic_to_global(src)) : "memory");
}
#define CP_COMMIT() asm volatile("cp.async.commit_group;" ::: "memory")
#define CP_WAIT1()  asm volatile("cp.async.wait_group 1;" ::: "memory")

__device__ __forceinline__ void ldsm4(uint32_t* r, uint32_t a) {
    asm volatile("ldmatrix.sync.aligned.m8n8.x4.shared.b16 {%0,%1,%2,%3}, [%4];"
                 : "=r"(r[0]), "=r"(r[1]), "=r"(r[2]), "=r"(r[3]) : "r"(a));
}
__device__ __forceinline__ void mma8(float* d, const uint32_t* a, const uint32_t* b) {
    asm volatile(
        "mma.sync.aligned.m16n8k8.row.col.f32.tf32.tf32.f32 "
        "{%0,%1,%2,%3},{%4,%5,%6,%7},{%8,%9},{%0,%1,%2,%3};\n"
        : "+f"(d[0]), "+f"(d[1]), "+f"(d[2]), "+f"(d[3])
        : "r"(a[0]), "r"(a[1]), "r"(a[2]), "r"(a[3]), "r"(b[0]), "r"(b[1]));
}

#define AP 36

// ---------------- one-shot: all 3 weight transposes (tf32 round) + counter zero ----------------
// z in [0,24): sel = z/8 (0:We1 1:We2 2:We3), e = z%8. Bounds guarded per sel.
__global__ void __launch_bounds__(256) transpose_all(
    const float* __restrict__ We1, const float* __restrict__ We2,
    const float* __restrict__ We3)
{
    __shared__ float t[32][33];
    const int sel = blockIdx.z >> 3, e = blockIdx.z & 7;
    const int K = (sel == 0) ? 256 : 512;
    const int N = (sel == 2) ? 256 : 512;
    if (blockIdx.x * 32 >= K || blockIdx.y * 32 >= N) return;
    if (blockIdx.x == 0 && blockIdx.y == 0 && blockIdx.z == 0 && threadIdx.x < E_)
        g_counts[threadIdx.x] = 0;
    const float* I = ((sel == 0) ? We1 : (sel == 1) ? We2 : We3) + (size_t)e * K * N;
    float* O = ((sel == 0) ? g_wT1 : (sel == 1) ? g_wT2 : g_wT3) + (size_t)e * K * N;
    const int k0 = blockIdx.x * 32, n0 = blockIdx.y * 32;
    const int tx = threadIdx.x & 31, ty = threadIdx.x >> 5;
    #pragma unroll
    for (int p = 0; p < 32; p += 8)
        t[ty + p][tx] = I[(size_t)(k0 + ty + p) * N + n0 + tx];
    __syncthreads();
    #pragma unroll
    for (int p = 0; p < 32; p += 8)
        O[(size_t)(n0 + ty + p) * K + k0 + tx] = __uint_as_float(f2tf(t[tx][ty + p]));
}

// ---------------- gating: register-tiled fp32 SGEMM (proven r11), routing bit-identical ----------------
#define GATE_DSMEM (128 * 132 * 4)
__global__ void __launch_bounds__(256, 2) gating_kernel(
    const float* __restrict__ x,  const float* __restrict__ gW1,
    const float* __restrict__ gb1, const float* __restrict__ gW2,
    const float* __restrict__ gb2)
{
    extern __shared__ float dsm[];            // staging As[8][132]+Bs[8][132]; later h[128][132]
    float* As = dsm;                          // [8][132]
    float* Bs = dsm + 8 * 132;                // [8][132]
    __shared__ float b1s[GH_], w2s[GH_ * E_], b2s[E_], logt[128 * E_];

    const int tid = threadIdx.x;
    const int tok0 = blockIdx.x * 128;
    if (tid < GH_) b1s[tid] = gb1[tid];
    for (int i = tid; i < GH_ * E_; i += 256) w2s[i] = gW2[i];
    if (tid < E_) b2s[tid] = gb2[tid];

    const int m_ld = tid & 127, half = tid >> 7;        // As staging coords
    const int kb_ld = tid >> 5, j_ld = (tid & 31) * 4;  // Bs staging coords
    const int tx = tid & 15, ty = tid >> 4;
    const int ma = ty * 4, jb = tx * 4;                 // micro-tile bases (+64 for upper half)

    float acc[8][8];
    #pragma unroll
    for (int i = 0; i < 8; ++i)
        #pragma unroll
        for (int j = 0; j < 8; ++j) acc[i][j] = 0.f;

    for (int kt = 0; kt < 32; ++kt) {
        const int k0 = kt * 8;
        float4 xa = *(const float4*)(x + (size_t)(tok0 + m_ld) * D_IN_ + k0 + half * 4);
        float4 wb = *(const float4*)(gW1 + (size_t)(k0 + kb_ld) * GH_ + j_ld);
        __syncthreads();                     // prior tile fully consumed
        As[(half * 4 + 0) * 132 + m_ld] = xa.x;
        As[(half * 4 + 1) * 132 + m_ld] = xa.y;
        As[(half * 4 + 2) * 132 + m_ld] = xa.z;
        As[(half * 4 + 3) * 132 + m_ld] = xa.w;
        *(float4*)(Bs + kb_ld * 132 + j_ld) = wb;
        __syncthreads();

        #pragma unroll
        for (int g = 0; g < 2; ++g) {
            #pragma unroll
            for (int kk = 3; kk >= 0; --kk) {      // descending within group: matches nesting
                const int k = g * 4 + kk;
                float4 a0 = *(const float4*)(As + k * 132 + ma);
                float4 a1 = *(const float4*)(As + k * 132 + 64 + ma);
                float4 b0 = *(const float4*)(Bs + k * 132 + jb);
                float4 b1 = *(const float4*)(Bs + k * 132 + 64 + jb);
                const float av[8] = {a0.x, a0.y, a0.z, a0.w, a1.x, a1.y, a1.z, a1.w};
                const float bv[8] = {b0.x, b0.y, b0.z, b0.w, b1.x, b1.y, b1.z, b1.w};
                #pragma unroll
                for (int i = 0; i < 8; ++i)
                    #pragma unroll
                    for (int j = 0; j < 8; ++j)
                        acc[i][j] = fmaf(av[i], bv[j], acc[i][j]);
            }
        }
    }
    __syncthreads();                         // staging dead; alias h over it

    // h = relu(acc + b1), to smem [128][132]
    float* hsm = dsm;
    #pragma unroll
    for (int i = 0; i < 8; ++i) {
        const int m = ma + (i & 3) + (i >> 2) * 64;
        #pragma unroll
        for (int j = 0; j < 8; ++j) {
            const int jj = jb + (j & 3) + (j >> 2) * 64;
            hsm[m * 132 + jj] = fmaxf(acc[i][j] + b1s[jj], 0.f);
        }
    }
    __syncthreads();

    // logits: 4 (token,expert) pairs per thread, identical ascending serial chain
    #pragma unroll
    for (int q = 0; q < 4; ++q) {
        const int pid = tid + q * 256;
        const int tok = pid >> 3, ee = pid & 7;
        float a = b2s[ee];
        const float* hrow = hsm + tok * 132;
        #pragma unroll 8
        for (int h = 0; h < 128; ++h) a = fmaf(hrow[h], w2s[h * 8 + ee], a);
        logt[tok * 8 + ee] = a;
    }
    __syncthreads();

    // top-2 + routing (identical selection logic)
    if (tid < 128) {
        float l[8];
        #pragma unroll
        for (int q = 0; q < 8; ++q) l[q] = logt[tid * 8 + q];
        int i1 = 0; float m1 = l[0];
        #pragma unroll
        for (int q = 1; q < 8; ++q) if (l[q] > m1) { m1 = l[q]; i1 = q; }
        int i2 = -1; float m2 = -1e30f;
        #pragma unroll
        for (int q = 0; q < 8; ++q) if (q != i1 && l[q] > m2) { m2 = l[q]; i2 = q; }
        const int t = tok0 + tid;
        const float ex  = expf(m2 - m1);
        const float den = 1.f + ex;
        int p1 = atomicAdd(&g_counts[i1], 1);
        g_list[i1 * B_ + p1] = t;
        int p2 = atomicAdd(&g_counts[i2], 1);
        g_list[i2 * B_ + p2] = t;
        g_pos[t * 2]     = i1 * CAP_ + p1;
        g_pos[t * 2 + 1] = i2 * CAP_ + p2;
        g_wtk[t * 2]     = 1.f / den;
        g_wtk[t * 2 + 1] = ex / den;
    }
}

// ---------------- tf32 mma.sync GEMM (proven r10 pipeline; gemm1 gathers x directly) ----------------
#define STG_BYTES   18432
#define STAGE_BYTES 36864
#define GEMM_DSMEM  110592

template<int K, int NTOT, int STAGE, bool RELU, bool TFROUND>
__global__ void __launch_bounds__(128, 2) gemm_mma(const float* __restrict__ bias,
                                                   const float* __restrict__ xsrc)
{
    const int e = blockIdx.z;
    const int cnt = g_counts[e];
    const int row0 = blockIdx.y * 128;     // y = row tile
    if (row0 >= cnt) return;
    const int n0 = blockIdx.x * 128;       // x = n tile (fast-varying -> A L2 reuse)

    extern __shared__ float dsm[];
    const uint32_t smBase = smem_u32(dsm);
    __shared__ int stok[128];

    const int tid = threadIdx.x;
    const int lid = tid & 31, wid = tid >> 5;
    const int g = lid >> 2, tg = lid & 3;
    const int wm = wid >> 1, wn = wid & 1;
    const int mb = wm * 64,  nb = wn * 64;

    const float* A  = (STAGE == 1) ? xsrc  : (STAGE == 2) ? g_h1 : g_h2;
    const float* Wt = (STAGE == 1) ? g_wT1 : (STAGE == 2) ? g_wT2 : g_wT3;
    float* Y = (STAGE == 1) ? g_h1 : (STAGE == 2) ? g_h2 : g_h1;   // stage3: y rows [.][256]
    const float* Ab = A + ((STAGE == 1) ? 0 : ((size_t)e * CAP_ + row0) * K);
    const float* Bb = Wt + ((size_t)e * NTOT + n0) * K;

    if (STAGE == 1) {   // index table: tile row -> token row of x
        int r = row0 + tid;
        stok[tid] = (r < cnt) ? g_list[e * B_ + r] : 0;
        __syncthreads();
    }

    const int lane_row = (lid & 7) + (((lid >> 3) & 1) << 3);
    const int lane_k   = (lid >> 4) * 4;
    uint32_t aAddr[4], bAddr[4];
    #pragma unroll
    for (int f = 0; f < 4; ++f)
        aAddr[f] = smBase + ((mb + f * 16 + lane_row) * AP + lane_k) * 4;
    {
        const int grp = lid >> 3;
        #pragma unroll
        for (int p = 0; p < 4; ++p) {
            const int n_loc = nb + (2 * p + (grp >> 1)) * 8 + (lid & 7);
            const int kcol  = (grp & 1) * 4;
            bAddr[p] = smBase + STG_BYTES + (n_loc * AP + kcol) * 4;
        }
    }

    float acc[4][8][4];
    #pragma unroll
    for (int f = 0; f < 4; ++f)
        #pragma unroll
        for (int j = 0; j < 8; ++j)
            #pragma unroll
            for (int q = 0; q < 4; ++q) acc[f][j][q] = 0.f;

    auto stage_copy = [&](int buf, int kt) {
        const uint32_t sb = smBase + buf * STAGE_BYTES;
        const int k0 = kt * 32;
        #pragma unroll
        for (int q = 0; q < 8; ++q) {
            const int c = q * 128 + tid;
            const int r = c >> 3, gg = (c & 7) * 4;
            const uint32_t doff = (r * AP + gg) * 4;
            const float* srcA = (STAGE == 1)
                ? Ab + (size_t)stok[r] * K + k0 + gg
                : Ab + (size_t)r * K + k0 + gg;
            cp16(sb + doff,             srcA);
            cp16(sb + STG_BYTES + doff, Bb + (size_t)r * K + k0 + gg);
        }
    };

    constexpr int KT = K / 32;
    stage_copy(0, 0); CP_COMMIT();
    stage_copy(1, 1); CP_COMMIT();
    for (int kt = 0; kt < KT; ++kt) {
        CP_WAIT1();                       // stage kt resident (group kt complete)
        __syncthreads();                  // all warps done reading stage (kt-1)%3
        if (kt + 2 < KT) stage_copy((kt + 2) % 3, kt + 2);   // refill freed stage
        CP_COMMIT();                      // unconditional: group arithmetic exact

        const uint32_t so = (kt % 3) * STAGE_BYTES;
        #pragma unroll
        for (int kk = 0; kk < 32; kk += 8) {
            uint32_t af[4][4], bf[8][2];
            #pragma unroll
            for (int f = 0; f < 4; ++f) ldsm4(af[f], aAddr[f] + so + kk * 4);
            #pragma unroll
            for (int p = 0; p < 4; ++p) {
                uint32_t bq[4];
                ldsm4(bq, bAddr[p] + so + kk * 4);
                bf[2 * p][0] = bq[0]; bf[2 * p][1] = bq[1];
                bf[2 * p + 1][0] = bq[2]; bf[2 * p + 1][1] = bq[3];
            }
            #pragma unroll
            for (int f = 0; f < 4; ++f)
                #pragma unroll
                for (int j = 0; j < 8; ++j)
                    mma8(acc[f][j], af[f], bf[j]);
        }
    }

    // ---------------- epilogue: plain stores (no atomics) ----------------
    const float* Bbias = bias + e * NTOT + n0;
    #pragma unroll
    for (int f = 0; f < 4; ++f) {
        const int rl = mb + f * 16 + g;
        #pragma unroll
        for (int j = 0; j < 8; ++j) {
            const int c = nb + j * 8 + 2 * tg;
            const float b0 = Bbias[c], b1 = Bbias[c + 1];
            float v00 = acc[f][j][0] + b0, v01 = acc[f][j][1] + b1;
            float v10 = acc[f][j][2] + b0, v11 = acc[f][j][3] + b1;
            if (RELU) {
                v00 = fmaxf(v00, 0.f); v01 = fmaxf(v01, 0.f);
                v10 = fmaxf(v10, 0.f); v11 = fmaxf(v11, 0.f);
            }
            if (row0 + rl < cnt) {
                float* p = Y + ((size_t)e * CAP_ + row0 + rl) * NTOT + n0 + c;
                if (TFROUND) { ((uint32_t*)p)[0] = f2tf(v00); ((uint32_t*)p)[1] = f2tf(v01); }
                else         { p[0] = v00; p[1] = v01; }
            }
            if (row0 + rl + 8 < cnt) {
                float* p = Y + ((size_t)e * CAP_ + row0 + rl + 8) * NTOT + n0 + c;
                if (TFROUND) { ((uint32_t*)p)[0] = f2tf(v10); ((uint32_t*)p)[1] = f2tf(v11); }
                else         { p[0] = v10; p[1] = v11; }
            }
        }
    }
}

// ---------------- combine: out[t] = w1*y[p1] + w2*y[p2] ----------------
__global__ void __launch_bounds__(256) combine_kernel(float* __restrict__ out) {
    const int idx = blockIdx.x * blockDim.x + threadIdx.x;    // B_*64 threads
    const int t = idx >> 6, q = idx & 63;
    const int p0 = g_pos[t * 2], p1 = g_pos[t * 2 + 1];
    const float w0 = g_wtk[t * 2], w1 = g_wtk[t * 2 + 1];
    const float4 a = ((const float4*)g_h1)[(size_t)p0 * 64 + q];
    const float4 b = ((const float4*)g_h1)[(size_t)p1 * 64 + q];
    float4 o;
    o.x = w0 * a.x + w1 * b.x;
    o.y = w0 * a.y + w1 * b.y;
    o.z = w0 * a.z + w1 * b.z;
    o.w = w0 * a.w + w1 * b.w;
    ((float4*)out)[(size_t)t * 64 + q] = o;
}

// ---------------- aux outputs ----------------
__global__ void finalize_kernel(float* __restrict__ out) {
    __shared__ float us[E_];
    const int e = threadIdx.x;
    if (e < E_) {
        float u = (float)g_counts[e] / (float)B_;
        us[e] = u;
        out[(size_t)B_ * D_OUT_ + 1 + e] = u;
    }
    __syncthreads();
    if (e == 0) {
        float s = 0.f;
        #pragma unroll
        for (int i = 0; i < E_; ++i) { float d = us[i] - (1.f / E_); s += d * d; }
        out[(size_t)B_ * D_OUT_] = (s / E_) * 0.01f;
    }
}

// ---------------- launch (gemm2 at slot 4 for ncu capture) ----------------
extern "C" void kernel_launch(void* const* d_in, const int* in_sizes, int n_in,
                              void* d_out, int out_size) {
    const float* x   = (const float*)d_in[0];
    const float* gW1 = (const float*)d_in[1];
    const float* gb1 = (const float*)d_in[2];
    const float* gW2 = (const float*)d_in[3];
    const float* gb2 = (const float*)d_in[4];
    const float* We1 = (const float*)d_in[5];
    const float* be1 = (const float*)d_in[6];
    const float* We2 = (const float*)d_in[7];
    const float* be2 = (const float*)d_in[8];
    const float* We3 = (const float*)d_in[9];
    const float* be3 = (const float*)d_in[10];
    float* out = (float*)d_out;

    cudaFuncSetAttribute(gating_kernel, cudaFuncAttributeMaxDynamicSharedMemorySize,
                         GATE_DSMEM);
    cudaFuncSetAttribute(gemm_mma<256, 512, 1, true,  true>,
                         cudaFuncAttributeMaxDynamicSharedMemorySize, GEMM_DSMEM);
    cudaFuncSetAttribute(gemm_mma<512, 512, 2, true,  true>,
                         cudaFuncAttributeMaxDynamicSharedMemorySize, GEMM_DSMEM);
    cudaFuncSetAttribute(gemm_mma<512, 256, 3, false, false>,
                         cudaFuncAttributeMaxDynamicSharedMemorySize, GEMM_DSMEM);

    transpose_all<<<dim3(16, 16, 24), 256>>>(We1, We2, We3);            // 1 (+ zero counts)
    gating_kernel<<<256, 256, GATE_DSMEM>>>(x, gW1, gb1, gW2, gb2);     // 2
    gemm_mma<256, 512, 1, true,  true ><<<dim3(4, CAP_ / 128, E_), 128, GEMM_DSMEM>>>(be1, x);       // 3
    gemm_mma<512, 512, 2, true,  true ><<<dim3(4, CAP_ / 128, E_), 128, GEMM_DSMEM>>>(be2, nullptr); // 4 <- profiled
    gemm_mma<512, 256, 3, false, false><<<dim3(2, CAP_ / 128, E_), 128, GEMM_DSMEM>>>(be3, nullptr); // 5
    combine_kernel<<<B_ * 64 / 256, 256>>>(out);                        // 6
    finalize_kernel<<<1, 32>>>(out);                                    // 7
}